// round 4
// baseline (speedup 1.0000x reference)
#include <cuda_runtime.h>
#include <cstdint>

// BinaryConv2d: x (8,16,1024,1024) f32, weight (16,16,3,3) in {0,1} -> +/-1
// stride (2,2), pad (1,1) -> out (8,16,512,512)
//
// R4: 2 px/thread, 256-thread blocks, 24 warps/SM (occupancy play).
// Warp-private tiles (2 output rows per warp), cp.async distance-2 pipeline,
// FFMA2 (f32x2) oc-pair-packed accumulators, zero block barriers in main loop.

#define N_BATCH 8
#define C_IN    16
#define C_OUT   16
#define IN_HW   1024
#define OUT_HW  512

#define TH 16              // output rows per block (2 per warp)
#define TW 32              // output cols per block
#define NTHREADS 256       // 8 warps
#define NBUF 3

#define ROW_STRIDE 68      // bulk row stride (floats), 272B
#define BULK_FLOATS (5 * ROW_STRIDE)    // 340
#define EDGE_OFF   340                  // edge column array (5 floats)
#define BUF_FLOATS 352                  // padded to 16B multiple

__device__ __forceinline__ unsigned long long bcast2(float x) {
    unsigned long long r;
    asm("mov.b64 %0, {%1, %1};" : "=l"(r) : "f"(x));
    return r;
}

__device__ __forceinline__ void ffma2(unsigned long long& acc,
                                      unsigned long long a,
                                      unsigned long long b) {
    asm("fma.rn.f32x2 %0, %1, %2, %0;" : "+l"(acc) : "l"(a), "l"(b));
}

__device__ __forceinline__ float2 unpack2(unsigned long long v) {
    float2 f;
    asm("mov.b64 {%0, %1}, %2;" : "=f"(f.x), "=f"(f.y) : "l"(v));
    return f;
}

__global__ void __launch_bounds__(NTHREADS, 3)
binconv_kernel(const float* __restrict__ x,
               const float* __restrict__ w,
               float* __restrict__ out) {
    __shared__ __align__(16) float s_tile[8][NBUF][BUF_FLOATS];
    __shared__ __align__(16) float s_sgn[C_IN * 9 * C_OUT];   // [c][tap][oc]

    const int tid  = threadIdx.x;
    const int wrp  = tid >> 5;          // 0..7 : 2-output-row band
    const int lane = tid & 31;
    const int tx   = lane & 15;         // x-group (2 output px)
    const int tyw  = lane >> 4;         // 0/1 : output row within band

    const int n  = blockIdx.z;
    const int y0 = blockIdx.y * TH;
    const int x0 = blockIdx.x * TW;

    // ---- decode weights into shared sign table (oc fastest) ----
    #pragma unroll
    for (int idx = tid; idx < C_OUT * C_IN * 9; idx += NTHREADS) {
        int oc  = idx / (C_IN * 9);
        int rem = idx - oc * (C_IN * 9);          // c*9 + tap
        s_sgn[rem * C_OUT + oc] = (w[idx] == 1.0f) ? 1.0f : -1.0f;
    }
    __syncthreads();   // only block barrier: sign table ready

    // ---- per-warp geometry ----
    const int gyw0 = 2 * (y0 + 2 * wrp) - 1;   // first input row of warp band (5 rows)
    const int gx1  = 2 * x0;                   // aligned bulk col base (= gx0+1)
    const bool edge_col_ok = (gx1 > 0);

    const float* xn = x + ((size_t)n << 24);
    const float* gbase = xn + (ptrdiff_t)gyw0 * IN_HW + gx1;

    const int prow0 = lane >> 4;               // row parity for bulk prefetch
    const int pcol  = (lane & 15) * 4;         // bulk col (floats)

    const uint32_t smem_w =
        (uint32_t)__cvta_generic_to_shared(&s_tile[wrp][0][0]);

    auto prefetch = [&](int c, int buf) {
        const float* gc = gbase + ((size_t)c << 20);
        uint32_t sb = smem_w + (uint32_t)buf * (BUF_FLOATS * 4);
        #pragma unroll
        for (int k = 0; k < 3; ++k) {
            int row = 2 * k + prow0;           // rows 0..5; skip 5
            if (k < 2 || prow0 == 0) {
                bool ok = (gyw0 + row) >= 0;   // only top row can be OOB
                const float* src = ok ? (gc + row * IN_HW + pcol) : xn;
                asm volatile("cp.async.cg.shared.global [%0], [%1], 16, %2;\n"
                             :: "r"(sb + (uint32_t)(row * ROW_STRIDE + pcol) * 4u),
                                "l"(src), "r"(ok ? 16 : 0));
            }
        }
        if (lane < 5) {
            bool ok = edge_col_ok && ((gyw0 + lane) >= 0);
            const float* src = ok ? (gc + lane * IN_HW - 1) : xn;
            asm volatile("cp.async.ca.shared.global [%0], [%1], 4, %2;\n"
                         :: "r"(sb + (uint32_t)(EDGE_OFF + lane) * 4u),
                            "l"(src), "r"(ok ? 4 : 0));
        }
        asm volatile("cp.async.commit_group;\n");
    };

    // accumulators: [oc_pair 0..7][px 0..1] packed f32x2
    unsigned long long acc[8][2];
    #pragma unroll
    for (int i = 0; i < 8; ++i) {
        acc[i][0] = 0ull;
        acc[i][1] = 0ull;
    }

    // ---- per-warp pipeline: distance 2, 3 buffers ----
    prefetch(0, 0);
    prefetch(1, 1);

    int ci = 0;
    int pi = 2;

    #pragma unroll 1
    for (int c = 0; c < C_IN; ++c) {
        if (c + 2 < C_IN) {
            prefetch(c + 2, pi);
            asm volatile("cp.async.wait_group 2;\n");
        } else if (c + 1 < C_IN) {
            asm volatile("cp.async.wait_group 1;\n");
        } else {
            asm volatile("cp.async.wait_group 0;\n");
        }
        __syncwarp();

        const float* bp = &s_tile[wrp][0][0] + ci * BUF_FLOATS;
        const float* sgn_c = s_sgn + c * 9 * C_OUT;

        #pragma unroll
        for (int r = 0; r < 3; ++r) {
            const int irow = 2 * tyw + r;
            const float* rpb = bp + irow * ROW_STRIDE;
            // x cols needed: 4tx-1 .. 4tx+3 (5 values)
            float xm1 = (tx == 0) ? bp[EDGE_OFF + irow] : rpb[4 * tx - 1];
            float4 A  = *(const float4*)(rpb + 4 * tx);

            unsigned long long xv[5];
            xv[0] = bcast2(xm1);
            xv[1] = bcast2(A.x); xv[2] = bcast2(A.y);
            xv[3] = bcast2(A.z); xv[4] = bcast2(A.w);

            #pragma unroll
            for (int j = 0; j < 3; ++j) {
                const ulonglong2* sp =
                    (const ulonglong2*)(sgn_c + (r * 3 + j) * C_OUT);
                ulonglong2 s0 = sp[0];   // broadcast LDS.128
                ulonglong2 s1 = sp[1];
                ulonglong2 s2 = sp[2];
                ulonglong2 s3 = sp[3];
                unsigned long long sv[8] =
                    { s0.x, s0.y, s1.x, s1.y, s2.x, s2.y, s3.x, s3.y };

                unsigned long long x0v = xv[j];      // px 0: col 2p-1+j
                unsigned long long x1v = xv[j + 2];  // px 1: col 2p+1+j
                #pragma unroll
                for (int i = 0; i < 8; ++i) {
                    ffma2(acc[i][0], x0v, sv[i]);
                    ffma2(acc[i][1], x1v, sv[i]);
                }
            }
        }
        __syncwarp();

        ci = (ci == 2) ? 0 : ci + 1;
        pi = (pi == 2) ? 0 : pi + 1;
    }

    // ---- writeout: 16 oc x 2 consecutive x -> float2 per oc ----
    const int oy = y0 + 2 * wrp + tyw;
    const int ox = x0 + 2 * tx;
    float* ob = out + (((size_t)n * C_OUT) * OUT_HW + oy) * OUT_HW + ox;

    #pragma unroll
    for (int i = 0; i < 8; ++i) {
        float2 f0 = unpack2(acc[i][0]);   // (oc 2i, oc 2i+1) @ px0
        float2 f1 = unpack2(acc[i][1]);   // (oc 2i, oc 2i+1) @ px1
        float2 lo = make_float2(f0.x, f1.x);
        float2 hi = make_float2(f0.y, f1.y);
        *(float2*)(ob + (size_t)(2 * i)     * OUT_HW * OUT_HW) = lo;
        *(float2*)(ob + (size_t)(2 * i + 1) * OUT_HW * OUT_HW) = hi;
    }
}

extern "C" void kernel_launch(void* const* d_in, const int* in_sizes, int n_in,
                              void* d_out, int out_size) {
    const float* x = (const float*)d_in[0];
    const float* w = (const float*)d_in[1];
    float* out = (float*)d_out;

    dim3 grid(OUT_HW / TW, OUT_HW / TH, N_BATCH);   // (16, 32, 8)
    dim3 block(NTHREADS);
    binconv_kernel<<<grid, block>>>(x, w, out);
}

// round 5
// speedup vs baseline: 1.1240x; 1.1240x over previous
#include <cuda_runtime.h>
#include <cstdint>

// BinaryConv2d: x (8,16,1024,1024) f32, weight (16,16,3,3) in {0,1} -> +/-1
// stride (2,2), pad (1,1) -> out (8,16,512,512)
//
// R5: R3 shape (4px/thread, warp-private 4-row bands) + channel-PAIR buffers
// (8 wait points instead of 16), NBUF=2, edge column folded into row stride.

#define N_BATCH 8
#define C_IN    16
#define C_OUT   16
#define IN_HW   1024
#define OUT_HW  512

#define TH 16              // output rows per block (4 per warp)
#define TW 32              // output cols per block
#define NTHREADS 128
#define NBUF 2

#define ROW_STRIDE 68      // floats; cols 0..63 bulk, col 67 = edge (x_{-1}) slot
#define CH_FLOATS  (9 * ROW_STRIDE)          // 612 (2448B, 16B multiple)
#define BUF_FLOATS (2 * CH_FLOATS)           // per pair-buffer

__device__ __forceinline__ unsigned long long bcast2(float x) {
    unsigned long long r;
    asm("mov.b64 %0, {%1, %1};" : "=l"(r) : "f"(x));
    return r;
}

__device__ __forceinline__ void ffma2(unsigned long long& acc,
                                      unsigned long long a,
                                      unsigned long long b) {
    asm("fma.rn.f32x2 %0, %1, %2, %0;" : "+l"(acc) : "l"(a), "l"(b));
}

__device__ __forceinline__ float2 unpack2(unsigned long long v) {
    float2 f;
    asm("mov.b64 {%0, %1}, %2;" : "=f"(f.x), "=f"(f.y) : "l"(v));
    return f;
}

__global__ void __launch_bounds__(NTHREADS, 4)
binconv_kernel(const float* __restrict__ x,
               const float* __restrict__ w,
               float* __restrict__ out) {
    __shared__ __align__(16) float s_tile[4][NBUF][BUF_FLOATS];   // 38.25 KB
    __shared__ __align__(16) float s_sgn[C_IN * 9 * C_OUT];       // 9 KB

    const int tid  = threadIdx.x;
    const int wrp  = tid >> 5;
    const int lane = tid & 31;
    const int tx   = lane & 7;          // x-group (4 output px)
    const int ty   = (lane >> 3) & 3;   // output row within warp band

    const int n  = blockIdx.z;
    const int y0 = blockIdx.y * TH;
    const int x0 = blockIdx.x * TW;

    // ---- decode weights into shared sign table (oc fastest) ----
    #pragma unroll
    for (int idx = tid; idx < C_OUT * C_IN * 9; idx += NTHREADS) {
        int oc  = idx / (C_IN * 9);
        int rem = idx - oc * (C_IN * 9);          // c*9 + tap
        s_sgn[rem * C_OUT + oc] = (w[idx] == 1.0f) ? 1.0f : -1.0f;
    }
    __syncthreads();   // only block barrier

    // ---- per-warp geometry ----
    const int gy0w = 2 * (y0 + 4 * wrp) - 1;   // first input row of 9-row band
    const int gx1  = 2 * x0;                   // aligned bulk col base
    const bool edge_col_ok = (gx1 > 0);

    const float* xn = x + ((size_t)n << 24);
    const float* gbase = xn + (ptrdiff_t)gy0w * IN_HW + gx1;

    const int brow_hi = lane >> 4;             // row parity for bulk prefetch
    const int bcol    = (lane & 15) * 4;       // bulk col (floats)

    const uint32_t smem_w =
        (uint32_t)__cvta_generic_to_shared(&s_tile[wrp][0][0]);

    // prefetch one channel PAIR (channels 2*cp, 2*cp+1) into buffer `buf`
    auto prefetch = [&](int cp, int buf) {
        uint32_t sb0 = smem_w + (uint32_t)buf * (BUF_FLOATS * 4);
        #pragma unroll
        for (int ch = 0; ch < 2; ++ch) {
            const float* gc = gbase + ((size_t)(2 * cp + ch) << 20);
            uint32_t sb = sb0 + (uint32_t)ch * (CH_FLOATS * 4);
            #pragma unroll
            for (int k = 0; k < 5; ++k) {
                int row = 2 * k + brow_hi;
                if (k < 4 || brow_hi == 0) {       // rows 0..8
                    bool ok = (gy0w + row) >= 0;
                    const float* src = ok ? (gc + row * IN_HW + bcol) : xn;
                    asm volatile("cp.async.cg.shared.global [%0], [%1], 16, %2;\n"
                                 :: "r"(sb + (uint32_t)(row * ROW_STRIDE + bcol) * 4u),
                                    "l"(src), "r"(ok ? 16 : 0));
                }
            }
            if (lane < 9) {    // edge col x_{-1} for each row -> col 67 slot
                bool ok = edge_col_ok && ((gy0w + lane) >= 0);
                const float* src = ok ? (gc + lane * IN_HW - 1) : xn;
                asm volatile("cp.async.ca.shared.global [%0], [%1], 4, %2;\n"
                             :: "r"(sb + (uint32_t)(lane * ROW_STRIDE + 67) * 4u),
                                "l"(src), "r"(ok ? 4 : 0));
            }
        }
        asm volatile("cp.async.commit_group;\n");
    };

    // accumulators: [oc_pair 0..7][px 0..3] packed f32x2
    unsigned long long acc[8][4];
    #pragma unroll
    for (int i = 0; i < 8; ++i)
        #pragma unroll
        for (int p = 0; p < 4; ++p)
            acc[i][p] = 0ull;

    // ---- per-warp pipeline: 8 channel-pairs, 2 buffers ----
    prefetch(0, 0);
    prefetch(1, 1);

    #pragma unroll 1
    for (int cp = 0; cp < 8; ++cp) {
        if (cp < 7) {
            asm volatile("cp.async.wait_group 1;\n");
        } else {
            asm volatile("cp.async.wait_group 0;\n");
        }
        __syncwarp();

        const int buf = cp & 1;
        const float* bpair = &s_tile[wrp][0][0] + buf * BUF_FLOATS;

        #pragma unroll
        for (int ch = 0; ch < 2; ++ch) {
            const float* bp = bpair + ch * CH_FLOATS;
            const float* sgn_c = s_sgn + (2 * cp + ch) * 9 * C_OUT;

            #pragma unroll
            for (int r = 0; r < 3; ++r) {
                const int irow = 2 * ty + r;
                const float* rpb = bp + irow * ROW_STRIDE;
                float xfirst = (tx == 0) ? rpb[67] : rpb[8 * tx - 1];
                float4 A = *(const float4*)(rpb + 8 * tx);
                float4 B = *(const float4*)(rpb + 8 * tx + 4);

                unsigned long long xv[9];
                xv[0] = bcast2(xfirst);
                xv[1] = bcast2(A.x); xv[2] = bcast2(A.y);
                xv[3] = bcast2(A.z); xv[4] = bcast2(A.w);
                xv[5] = bcast2(B.x); xv[6] = bcast2(B.y);
                xv[7] = bcast2(B.z); xv[8] = bcast2(B.w);

                #pragma unroll
                for (int j = 0; j < 3; ++j) {
                    const ulonglong2* sp =
                        (const ulonglong2*)(sgn_c + (r * 3 + j) * C_OUT);
                    ulonglong2 s0 = sp[0];   // broadcast LDS.128
                    ulonglong2 s1 = sp[1];
                    ulonglong2 s2 = sp[2];
                    ulonglong2 s3 = sp[3];
                    unsigned long long sv[8] =
                        { s0.x, s0.y, s1.x, s1.y, s2.x, s2.y, s3.x, s3.y };

                    #pragma unroll
                    for (int p = 0; p < 4; ++p) {
                        unsigned long long xvp = xv[2 * p + j];
                        #pragma unroll
                        for (int i = 0; i < 8; ++i)
                            ffma2(acc[i][p], xvp, sv[i]);
                    }
                }
            }
        }
        __syncwarp();

        // refill this buffer with pair cp+2 (write-after-read: same warp,
        // gmem latency >> LDS completion, and next touch is 1 full pair away)
        if (cp + 2 < 8)
            prefetch(cp + 2, buf);
    }

    // ---- writeout: 16 oc x 4 consecutive x -> float4 per oc ----
    const int oy = y0 + 4 * wrp + ty;
    const int ox = x0 + 4 * tx;
    float* ob = out + (((size_t)n * C_OUT) * OUT_HW + oy) * OUT_HW + ox;

    #pragma unroll
    for (int i = 0; i < 8; ++i) {
        float2 f0 = unpack2(acc[i][0]);
        float2 f1 = unpack2(acc[i][1]);
        float2 f2 = unpack2(acc[i][2]);
        float2 f3 = unpack2(acc[i][3]);
        float4 lo = make_float4(f0.x, f1.x, f2.x, f3.x);
        float4 hi = make_float4(f0.y, f1.y, f2.y, f3.y);
        *(float4*)(ob + (size_t)(2 * i)     * OUT_HW * OUT_HW) = lo;
        *(float4*)(ob + (size_t)(2 * i + 1) * OUT_HW * OUT_HW) = hi;
    }
}

extern "C" void kernel_launch(void* const* d_in, const int* in_sizes, int n_in,
                              void* d_out, int out_size) {
    const float* x = (const float*)d_in[0];
    const float* w = (const float*)d_in[1];
    float* out = (float*)d_out;

    dim3 grid(OUT_HW / TW, OUT_HW / TH, N_BATCH);   // (16, 32, 8)
    dim3 block(NTHREADS);
    binconv_kernel<<<grid, block>>>(x, w, out);
}